// round 2
// baseline (speedup 1.0000x reference)
#include <cuda_runtime.h>

// Problem dims
// N=32, T=64, D=16, F=512; graphs = N*T = 2048

// Scratch (allocation-free: __device__ globals)
__device__ float g_obj[2048 * 16 * 512];   // 64 MB
__device__ float g_feat[2048 * 512];       // 4 MB
__device__ float g_c[2048 * 1024];         // 8 MB
__device__ float g_cbar[32 * 1024];        // 128 KB

// ---------------------------------------------------------------------------
// Tiled fp32 GEMM: C[row*ldc + coff + col] = (RELU?) (A@B + bias)
// A: [M,K] row-major, B: [K,N] row-major. Requires M%128==0, N%128==0, K%8==0.
// BM=BN=128, BK=8, 8x8 micro-tile, 256 threads.
// ---------------------------------------------------------------------------
template <bool RELU>
__global__ __launch_bounds__(256) void gemm_bias(
    const float* __restrict__ A, const float* __restrict__ B,
    const float* __restrict__ bias, float* __restrict__ C,
    int M, int N, int K, int ldc, int coff)
{
    __shared__ float As[8][132];   // padded: conflict-free transposed stores
    __shared__ float Bs[8][128];

    const int t  = threadIdx.x;
    const int bm = blockIdx.y * 128;
    const int bn = blockIdx.x * 128;
    const int tm = (t >> 4) * 8;
    const int tn = (t & 15) * 8;

    const int arow = t >> 1, akc = (t & 1) * 4;   // A: row, k-offset (float4)
    const int bkr  = t >> 5, bnc = (t & 31) * 4;  // B: k-row, n-offset (float4)

    const float* Aptr = A + (size_t)(bm + arow) * K + akc;
    const float* Bptr = B + (size_t)bkr * N + bn + bnc;

    float acc[8][8];
#pragma unroll
    for (int i = 0; i < 8; i++)
#pragma unroll
        for (int j = 0; j < 8; j++) acc[i][j] = 0.f;

    for (int k0 = 0; k0 < K; k0 += 8) {
        float4 av = *(const float4*)(Aptr + k0);
        As[akc + 0][arow] = av.x;
        As[akc + 1][arow] = av.y;
        As[akc + 2][arow] = av.z;
        As[akc + 3][arow] = av.w;
        *(float4*)(&Bs[bkr][bnc]) = *(const float4*)(Bptr + (size_t)k0 * N);
        __syncthreads();

#pragma unroll
        for (int kk = 0; kk < 8; kk++) {
            float a[8], b[8];
            *(float4*)(a)     = *(const float4*)(&As[kk][tm]);
            *(float4*)(a + 4) = *(const float4*)(&As[kk][tm + 4]);
            *(float4*)(b)     = *(const float4*)(&Bs[kk][tn]);
            *(float4*)(b + 4) = *(const float4*)(&Bs[kk][tn + 4]);
#pragma unroll
            for (int i = 0; i < 8; i++)
#pragma unroll
                for (int j = 0; j < 8; j++) acc[i][j] += a[i] * b[j];
        }
        __syncthreads();
    }

#pragma unroll
    for (int i = 0; i < 8; i++) {
        int row = bm + tm + i;
#pragma unroll
        for (int j = 0; j < 8; j += 4) {
            int col = bn + tn + j;
            float4 bv = *(const float4*)(bias + col);
            float4 o;
            o.x = acc[i][j + 0] + bv.x;
            o.y = acc[i][j + 1] + bv.y;
            o.z = acc[i][j + 2] + bv.z;
            o.w = acc[i][j + 3] + bv.w;
            if (RELU) {
                o.x = fmaxf(o.x, 0.f); o.y = fmaxf(o.y, 0.f);
                o.z = fmaxf(o.z, 0.f); o.w = fmaxf(o.w, 0.f);
            }
            *(float4*)(C + (size_t)row * ldc + coff + col) = o;
        }
    }
}

// ---------------------------------------------------------------------------
// Per-graph GCN kernel: one block (256 thr) per graph of x = obj[g] : [16,512].
// Produces feat[g][:] = relu( (mean_D(obj) + 0.5*(mean_D x1 + mean_D y2)) * 0.5 )
// using the linearity trick: mean_i (adj @ t)[i][c] = sum_j (mean_i adj[i][j]) t[j][c].
// ---------------------------------------------------------------------------
#define XS 516   // padded x stride (reduces smem bank conflicts in x@x^T)

__global__ __launch_bounds__(256) void graph_kernel(
    const float* __restrict__ obj,
    const float* __restrict__ gc1_W, const float* __restrict__ gc1_b,
    const float* __restrict__ gc2_W, const float* __restrict__ gc2_b,
    const float* __restrict__ gc3_W, const float* __restrict__ gc3_b,
    const float* __restrict__ gc4_W, const float* __restrict__ gc4_b,
    float* __restrict__ feat)
{
    __shared__ float sx[16 * XS];     // x tile [16,512] (33 KB)
    __shared__ float s_adj[16][17];   // s, then exp, then normalized adj
    __shared__ float s_a3[16][17];    // y22, then adj3, then adj_hat3
    __shared__ float s_w1[16][33];    // x @ gc1_W
    __shared__ float s_w3[16][33];    // x @ gc3_W
    __shared__ float s_h1[16][33];    // relu(adj@xw1 + b1)
    __shared__ float s_y2[16][33];    // relu(adj@xw3 + b3)
    __shared__ float s_d[16], s_m1[16], s_m3[16];
    __shared__ float s_hbar[32], s_ybar[32];

    const int g = blockIdx.x;
    const int t = threadIdx.x;
    const float* x = obj + (size_t)g * 16 * 512;

    // load x -> smem (float4)
    for (int idx = t * 4; idx < 16 * 512; idx += 256 * 4) {
        int i = idx >> 9, k = idx & 511;
        *(float4*)(sx + i * XS + k) = *(const float4*)(x + idx);
    }
    __syncthreads();

    // omean (mean over D of obj) in registers: this thread owns cols t, t+256
    const int c0 = t, c1 = t + 256;
    float om0 = 0.f, om1 = 0.f;
#pragma unroll
    for (int i = 0; i < 16; i++) { om0 += sx[i * XS + c0]; om1 += sx[i * XS + c1]; }
    om0 *= (1.f / 16.f); om1 *= (1.f / 16.f);

    // s = x @ x^T  (thread (i,j) -> 512-dot)
    {
        const int i = t >> 4, j = t & 15;
        float acc = 0.f;
        for (int k = 0; k < 512; k++) acc += sx[i * XS + k] * sx[j * XS + k];
        s_adj[i][j] = acc;
    }
    // xw1 = x@gc1_W, xw3 = x@gc3_W  ([16,32], 2 rows/thread), fused over shared x
    {
        const int j = t & 31, i0 = t >> 5;
        float a1a = 0, a1b = 0, a3a = 0, a3b = 0;
        for (int k = 0; k < 512; k++) {
            float w1 = gc1_W[k * 32 + j], w3 = gc3_W[k * 32 + j];
            float xa = sx[i0 * XS + k], xb = sx[(i0 + 8) * XS + k];
            a1a += xa * w1; a3a += xa * w3;
            a1b += xb * w1; a3b += xb * w3;
        }
        s_w1[i0][j] = a1a; s_w1[i0 + 8][j] = a1b;
        s_w3[i0][j] = a3a; s_w3[i0 + 8][j] = a3b;
    }
    __syncthreads();

    // adjacency: row softmax-exp + D^{-1/2}
    if (t < 16) {
        float mx = -1e30f;
#pragma unroll
        for (int j = 0; j < 16; j++) mx = fmaxf(mx, s_adj[t][j]);
        float sum = 0.f;
#pragma unroll
        for (int j = 0; j < 16; j++) { float e = expf(s_adj[t][j] - mx); s_adj[t][j] = e; sum += e; }
        s_d[t] = rsqrtf(sum);
    }
    __syncthreads();
    {
        const int i = t >> 4, j = t & 15;
        s_adj[i][j] = s_adj[i][j] * s_d[i] * s_d[j];
    }
    __syncthreads();

    // m1[j] = mean_i adj[i][j] ; and h1/y2 = relu(adj @ xw + b) (adj read-only here)
    if (t < 16) {
        float s = 0.f;
#pragma unroll
        for (int i = 0; i < 16; i++) s += s_adj[i][t];
        s_m1[t] = s * (1.f / 16.f);
    }
    {
        const int j = t & 31, i0 = t >> 5;
#pragma unroll
        for (int rep = 0; rep < 2; rep++) {
            const int i = i0 + rep * 8;
            float a1 = gc1_b[j], a3 = gc3_b[j];
#pragma unroll
            for (int l = 0; l < 16; l++) {
                float ad = s_adj[i][l];
                a1 += ad * s_w1[l][j];
                a3 += ad * s_w3[l][j];
            }
            s_h1[i][j] = fmaxf(a1, 0.f);
            s_y2[i][j] = fmaxf(a3, 0.f);
        }
    }
    __syncthreads();

    // y22 = y2 @ y2^T
    {
        const int i = t >> 4, j = t & 15;
        float acc = 0.f;
#pragma unroll
        for (int l = 0; l < 32; l++) acc += s_y2[i][l] * s_y2[j][l];
        s_a3[i][j] = acc;
    }
    __syncthreads();
    // nrm[i] = ||y22_row_i||_2
    if (t < 16) {
        float ss = 0.f;
#pragma unroll
        for (int j = 0; j < 16; j++) { float v = s_a3[t][j]; ss += v * v; }
        s_d[t] = sqrtf(ss);
    }
    __syncthreads();
    // adj3 = 1 + y22/(nrm_i*nrm_j)
    {
        const int i = t >> 4, j = t & 15;
        s_a3[i][j] = 1.f + s_a3[i][j] / (s_d[i] * s_d[j]);
    }
    __syncthreads();
    // D^{-1/2} normalize adj3
    if (t < 16) {
        float sum = 0.f;
#pragma unroll
        for (int j = 0; j < 16; j++) sum += s_a3[t][j];
        s_d[t] = rsqrtf(sum);
    }
    __syncthreads();
    {
        const int i = t >> 4, j = t & 15;
        s_a3[i][j] = s_a3[i][j] * s_d[i] * s_d[j];
    }
    __syncthreads();
    // m3[j] = mean_i adj_hat3[i][j]
    if (t < 16) {
        float s = 0.f;
#pragma unroll
        for (int i = 0; i < 16; i++) s += s_a3[i][t];
        s_m3[t] = s * (1.f / 16.f);
    }
    __syncthreads();

    // hbar[l] = sum_j m1[j]*h1[j][l];  ybar[l] = sum_j m3[j]*y2[j][l]
    if (t < 32) {
        float s = 0.f;
#pragma unroll
        for (int j = 0; j < 16; j++) s += s_m1[j] * s_h1[j][t];
        s_hbar[t] = s;
    } else if (t < 64) {
        const int l = t - 32;
        float s = 0.f;
#pragma unroll
        for (int j = 0; j < 16; j++) s += s_m3[j] * s_y2[j][l];
        s_ybar[l] = s;
    }
    __syncthreads();

    // gsum[c] = (hbar @ gc2_W)[c] + gc2_b[c] + (ybar @ gc4_W)[c] + gc4_b[c]
    float gm0 = gc2_b[c0] + gc4_b[c0];
    float gm1 = gc2_b[c1] + gc4_b[c1];
#pragma unroll
    for (int l = 0; l < 32; l++) {
        float hb = s_hbar[l], yb = s_ybar[l];
        gm0 += hb * gc2_W[l * 512 + c0] + yb * gc4_W[l * 512 + c0];
        gm1 += hb * gc2_W[l * 512 + c1] + yb * gc4_W[l * 512 + c1];
    }

    // feat = relu((omean + 0.5*gsum)*0.5)
    feat[(size_t)g * 512 + c0] = fmaxf((om0 + 0.5f * gm0) * 0.5f, 0.f);
    feat[(size_t)g * 512 + c1] = fmaxf((om1 + 0.5f * gm1) * 0.5f, 0.f);
}

// ---------------------------------------------------------------------------
// cbar[n][k] = mean_t c[(n*64+t)][k]   (mean over T before clf: linearity)
// ---------------------------------------------------------------------------
__global__ void reduce_T(const float* __restrict__ c, float* __restrict__ cbar)
{
    const int n = blockIdx.y;
    const int k = blockIdx.x * 256 + threadIdx.x;   // 0..1023
    float s = 0.f;
#pragma unroll 8
    for (int tt = 0; tt < 64; tt++)
        s += c[(size_t)(n * 64 + tt) * 1024 + k];
    cbar[n * 1024 + k] = s * (1.f / 64.f);
}

// ---------------------------------------------------------------------------
// out[n][j] = cbar[n] @ clf_W[:,j] + clf_b[j]   (32 x 500, K=1024)
// ---------------------------------------------------------------------------
__global__ __launch_bounds__(512) void clf_kernel(
    const float* __restrict__ cbar, const float* __restrict__ W,
    const float* __restrict__ b, float* __restrict__ out)
{
    __shared__ float sc[1024];
    const int n = blockIdx.x;
    for (int k = threadIdx.x; k < 1024; k += 512) sc[k] = cbar[n * 1024 + k];
    __syncthreads();
    const int j = threadIdx.x;
    if (j < 500) {
        float acc = b[j];
        for (int k = 0; k < 1024; k++) acc += sc[k] * W[k * 500 + j];
        out[n * 500 + j] = acc;
    }
}

// ---------------------------------------------------------------------------
extern "C" void kernel_launch(void* const* d_in, const int* in_sizes, int n_in,
                              void* d_out, int out_size)
{
    const float* object_raw = (const float*)d_in[0];
    const float* action_raw = (const float*)d_in[1];
    const float* W_obj = (const float*)d_in[2];
    const float* b_obj = (const float*)d_in[3];
    const float* W_act = (const float*)d_in[4];
    const float* b_act = (const float*)d_in[5];
    const float* gc1_W = (const float*)d_in[6];
    const float* gc1_b = (const float*)d_in[7];
    const float* gc2_W = (const float*)d_in[8];
    const float* gc2_b = (const float*)d_in[9];
    const float* gc3_W = (const float*)d_in[10];
    const float* gc3_b = (const float*)d_in[11];
    const float* gc4_W = (const float*)d_in[12];
    const float* gc4_b = (const float*)d_in[13];
    const float* fc1_W = (const float*)d_in[14];
    const float* fc1_b = (const float*)d_in[15];
    const float* clf_W = (const float*)d_in[16];
    const float* clf_b = (const float*)d_in[17];
    float* out = (float*)d_out;

    float *p_obj, *p_feat, *p_c, *p_cbar;
    cudaGetSymbolAddress((void**)&p_obj, g_obj);
    cudaGetSymbolAddress((void**)&p_feat, g_feat);
    cudaGetSymbolAddress((void**)&p_c, g_c);
    cudaGetSymbolAddress((void**)&p_cbar, g_cbar);

    // 1) obj = relu(object_raw @ W_obj + b_obj)  -> [32768,512] laid out [2048,16,512]
    gemm_bias<true><<<dim3(512 / 128, 32768 / 128), 256>>>(
        object_raw, W_obj, b_obj, p_obj, 32768, 512, 512, 512, 0);

    // 2) act = relu(action_raw @ W_act + b_act) -> overwrite middle frame (d=8)
    gemm_bias<true><<<dim3(512 / 128, 2048 / 128), 256>>>(
        action_raw, W_act, b_act, p_obj, 2048, 512, 512, 16 * 512, 8 * 512);

    // 3) per-graph GCN + D-mean fusion -> feat = relu((o + g)*0.5) : [2048,512]
    graph_kernel<<<2048, 256>>>(p_obj, gc1_W, gc1_b, gc2_W, gc2_b,
                                gc3_W, gc3_b, gc4_W, gc4_b, p_feat);

    // 4) c = relu(feat @ fc1_W + fc1_b) : [2048,1024]
    gemm_bias<true><<<dim3(1024 / 128, 2048 / 128), 256>>>(
        p_feat, fc1_W, fc1_b, p_c, 2048, 1024, 512, 1024, 0);

    // 5) mean over T -> cbar [32,1024]
    reduce_T<<<dim3(4, 32), 256>>>(p_c, p_cbar);

    // 6) out = cbar @ clf_W + clf_b : [32,500]
    clf_kernel<<<32, 512>>>(p_cbar, clf_W, clf_b, out);
}

// round 5
// speedup vs baseline: 2.0471x; 2.0471x over previous
#include <cuda_runtime.h>
#include <cstdint>
#include <cstddef>

// N=32, T=64, D=16, F=512; graphs = 2048. All big GEMM K = 512.

// -------- scratch (allocation-free) --------
__device__ float g_obj[2048 * 16 * 512];   // 64 MB
__device__ float g_feat[2048 * 512];       // 4 MB
__device__ float g_c[2048 * 1024];         // 8 MB
__device__ float g_cbar[32 * 1024];

#define DINL __device__ __forceinline__

DINL uint32_t s2u(const void* p) {
    uint32_t a;
    asm("{ .reg .u64 t; cvta.to.shared.u64 t, %1; cvt.u32.u64 %0, t; }" : "=r"(a) : "l"(p));
    return a;
}
DINL void cp16(uint32_t s, const void* g) {
    asm volatile("cp.async.cg.shared.global [%0], [%1], 16;" :: "r"(s), "l"(g));
}
DINL void cp_commit() { asm volatile("cp.async.commit_group;" ::: "memory"); }
DINL void cp_wait2()  { asm volatile("cp.async.wait_group 2;" ::: "memory"); }
DINL uint32_t f2tf(float f) {
    uint32_t u;
    asm("cvt.rna.tf32.f32 %0, %1;" : "=r"(u) : "f"(f));
    return u;
}
DINL void mma_tf32(float* c, const uint32_t* a, const uint32_t* b) {
    asm volatile(
        "mma.sync.aligned.m16n8k8.row.col.f32.tf32.tf32.f32 "
        "{%0,%1,%2,%3}, {%4,%5,%6,%7}, {%8,%9}, {%0,%1,%2,%3};"
        : "+f"(c[0]), "+f"(c[1]), "+f"(c[2]), "+f"(c[3])
        : "r"(a[0]), "r"(a[1]), "r"(a[2]), "r"(a[3]), "r"(b[0]), "r"(b[1]));
}

// ---------------------------------------------------------------------------
// Tensor-core tf32 GEMM: C[(bm+r)*ldc + coff + c] = relu(A@B + bias)
// A: [M,K] row-major; B: [K,Nb] row-major (natural weight layout, no transpose).
// BM=BN=128, BK=32, 3-stage cp.async pipeline, 256 thr = 8 warps (4x2),
// warp tile 32x64 = 2x8 m16n8k8 fragments. M%128==0, Nb%128? (grid covers), K%32==0.
// ---------------------------------------------------------------------------
#define AST 36   // A smem row stride (floats): banks 4g+tg unique, 144B = 9*16B
#define BST 136  // B smem row stride (floats): banks 8tg+g unique, 544B = 34*16B

__global__ __launch_bounds__(256) void tgemm(
    const float* __restrict__ A, const float* __restrict__ B,
    const float* __restrict__ bias, float* __restrict__ C,
    int K, int Nb, int ldc, int coff)
{
    extern __shared__ float smf[];
    float* sA = smf;                  // 3 stages * 128*36
    float* sB = smf + 3 * 128 * AST;  // 3 stages * 32*136

    const int t = threadIdx.x;
    const int lane = t & 31, wid = t >> 5;
    const int wm = wid & 3, wn = wid >> 2;       // warp grid 4x2
    const int g = lane >> 2, tg = lane & 3;      // fragment coords
    const long bm = (long)blockIdx.y * 128;
    const int bn = blockIdx.x * 128;
    const int nK = K >> 5;

    auto LOAD = [&](int j) {
        const int s = j % 3;
        float* a0 = sA + s * (128 * AST);
        float* b0 = sB + s * (32 * BST);
        const float* Ag = A + (size_t)bm * K + j * 32;
        const float* Bg = B + (size_t)(j * 32) * Nb + bn;
#pragma unroll
        for (int r = 0; r < 4; r++) {
            int i = t + 256 * r;
            int row = i >> 3, seg = i & 7;                     // A: 128 rows x 8 segs
            cp16(s2u(a0 + row * AST + seg * 4), Ag + (size_t)row * K + seg * 4);
            int kr = i >> 5, sg = i & 31;                      // B: 32 rows x 32 segs
            cp16(s2u(b0 + kr * BST + sg * 4), Bg + (size_t)kr * Nb + sg * 4);
        }
        cp_commit();
    };

    float acc[2][8][4];
#pragma unroll
    for (int m = 0; m < 2; m++)
#pragma unroll
        for (int n = 0; n < 8; n++)
#pragma unroll
            for (int q = 0; q < 4; q++) acc[m][n][q] = 0.f;

    LOAD(0); LOAD(1); LOAD(2);

    for (int i = 0; i < nK; i++) {
        cp_wait2();
        __syncthreads();
        const int s = i % 3;
        const float* As_ = sA + s * (128 * AST) + (wm * 32) * AST;
        const float* Bs_ = sB + s * (32 * BST) + wn * 64;
#pragma unroll
        for (int ks = 0; ks < 4; ks++) {
            uint32_t af[2][4];
#pragma unroll
            for (int m = 0; m < 2; m++) {
                const float* ap = As_ + (m * 16 + g) * AST + ks * 8 + tg;
                af[m][0] = f2tf(ap[0]);
                af[m][1] = f2tf(ap[8 * AST]);
                af[m][2] = f2tf(ap[4]);
                af[m][3] = f2tf(ap[8 * AST + 4]);
            }
            uint32_t bf[8][2];
#pragma unroll
            for (int n = 0; n < 8; n++) {
                const float* bp = Bs_ + (ks * 8 + tg) * BST + n * 8 + g;
                bf[n][0] = f2tf(bp[0]);
                bf[n][1] = f2tf(bp[4 * BST]);
            }
#pragma unroll
            for (int m = 0; m < 2; m++)
#pragma unroll
                for (int n = 0; n < 8; n++) mma_tf32(acc[m][n], af[m], bf[n]);
        }
        __syncthreads();
        if (i + 3 < nK) LOAD(i + 3);
    }

    // epilogue: bias + relu, float2 stores
#pragma unroll
    for (int m = 0; m < 2; m++) {
        const long row0 = bm + wm * 32 + m * 16 + g;
#pragma unroll
        for (int n = 0; n < 8; n++) {
            const int col = bn + wn * 64 + n * 8 + 2 * tg;
            const float b0 = bias[col], b1 = bias[col + 1];
            float2 v0, v1;
            v0.x = fmaxf(acc[m][n][0] + b0, 0.f);
            v0.y = fmaxf(acc[m][n][1] + b1, 0.f);
            v1.x = fmaxf(acc[m][n][2] + b0, 0.f);
            v1.y = fmaxf(acc[m][n][3] + b1, 0.f);
            *(float2*)(C + (size_t)row0 * ldc + coff + col) = v0;
            *(float2*)(C + (size_t)(row0 + 8) * ldc + coff + col) = v1;
        }
    }
}

// ---------------------------------------------------------------------------
// Per-graph GCN (known correct from round 0).
// ---------------------------------------------------------------------------
#define XS 516

__global__ __launch_bounds__(256) void graph_kernel(
    const float* __restrict__ obj,
    const float* __restrict__ gc1_W, const float* __restrict__ gc1_b,
    const float* __restrict__ gc2_W, const float* __restrict__ gc2_b,
    const float* __restrict__ gc3_W, const float* __restrict__ gc3_b,
    const float* __restrict__ gc4_W, const float* __restrict__ gc4_b,
    float* __restrict__ feat)
{
    __shared__ float sx[16 * XS];
    __shared__ float s_adj[16][17];
    __shared__ float s_a3[16][17];
    __shared__ float s_w1[16][33];
    __shared__ float s_w3[16][33];
    __shared__ float s_h1[16][33];
    __shared__ float s_y2[16][33];
    __shared__ float s_d[16], s_m1[16], s_m3[16];
    __shared__ float s_hbar[32], s_ybar[32];

    const int gidx = blockIdx.x;
    const int t = threadIdx.x;
    const float* x = obj + (size_t)gidx * 16 * 512;

    for (int idx = t * 4; idx < 16 * 512; idx += 256 * 4) {
        int i = idx >> 9, k = idx & 511;
        *(float4*)(sx + i * XS + k) = *(const float4*)(x + idx);
    }
    __syncthreads();

    const int c0 = t, c1 = t + 256;
    float om0 = 0.f, om1 = 0.f;
#pragma unroll
    for (int i = 0; i < 16; i++) { om0 += sx[i * XS + c0]; om1 += sx[i * XS + c1]; }
    om0 *= 0.0625f; om1 *= 0.0625f;

    {
        const int i = t >> 4, j = t & 15;
        float acc = 0.f;
        for (int k = 0; k < 512; k++) acc += sx[i * XS + k] * sx[j * XS + k];
        s_adj[i][j] = acc;
    }
    {
        const int j = t & 31, i0 = t >> 5;
        float a1a = 0, a1b = 0, a3a = 0, a3b = 0;
        for (int k = 0; k < 512; k++) {
            float w1 = gc1_W[k * 32 + j], w3 = gc3_W[k * 32 + j];
            float xa = sx[i0 * XS + k], xb = sx[(i0 + 8) * XS + k];
            a1a += xa * w1; a3a += xa * w3;
            a1b += xb * w1; a3b += xb * w3;
        }
        s_w1[i0][j] = a1a; s_w1[i0 + 8][j] = a1b;
        s_w3[i0][j] = a3a; s_w3[i0 + 8][j] = a3b;
    }
    __syncthreads();

    if (t < 16) {
        float mx = -1e30f;
#pragma unroll
        for (int j = 0; j < 16; j++) mx = fmaxf(mx, s_adj[t][j]);
        float sum = 0.f;
#pragma unroll
        for (int j = 0; j < 16; j++) { float e = expf(s_adj[t][j] - mx); s_adj[t][j] = e; sum += e; }
        s_d[t] = rsqrtf(sum);
    }
    __syncthreads();
    {
        const int i = t >> 4, j = t & 15;
        s_adj[i][j] = s_adj[i][j] * s_d[i] * s_d[j];
    }
    __syncthreads();

    if (t < 16) {
        float s = 0.f;
#pragma unroll
        for (int i = 0; i < 16; i++) s += s_adj[i][t];
        s_m1[t] = s * 0.0625f;
    }
    {
        const int j = t & 31, i0 = t >> 5;
#pragma unroll
        for (int rep = 0; rep < 2; rep++) {
            const int i = i0 + rep * 8;
            float a1 = gc1_b[j], a3 = gc3_b[j];
#pragma unroll
            for (int l = 0; l < 16; l++) {
                float ad = s_adj[i][l];
                a1 += ad * s_w1[l][j];
                a3 += ad * s_w3[l][j];
            }
            s_h1[i][j] = fmaxf(a1, 0.f);
            s_y2[i][j] = fmaxf(a3, 0.f);
        }
    }
    __syncthreads();

    {
        const int i = t >> 4, j = t & 15;
        float acc = 0.f;
#pragma unroll
        for (int l = 0; l < 32; l++) acc += s_y2[i][l] * s_y2[j][l];
        s_a3[i][j] = acc;
    }
    __syncthreads();
    if (t < 16) {
        float ss = 0.f;
#pragma unroll
        for (int j = 0; j < 16; j++) { float v = s_a3[t][j]; ss += v * v; }
        s_d[t] = sqrtf(ss);
    }
    __syncthreads();
    {
        const int i = t >> 4, j = t & 15;
        s_a3[i][j] = 1.f + s_a3[i][j] / (s_d[i] * s_d[j]);
    }
    __syncthreads();
    if (t < 16) {
        float sum = 0.f;
#pragma unroll
        for (int j = 0; j < 16; j++) sum += s_a3[t][j];
        s_d[t] = rsqrtf(sum);
    }
    __syncthreads();
    {
        const int i = t >> 4, j = t & 15;
        s_a3[i][j] = s_a3[i][j] * s_d[i] * s_d[j];
    }
    __syncthreads();
    if (t < 16) {
        float s = 0.f;
#pragma unroll
        for (int i = 0; i < 16; i++) s += s_a3[i][t];
        s_m3[t] = s * 0.0625f;
    }
    __syncthreads();

    if (t < 32) {
        float s = 0.f;
#pragma unroll
        for (int j = 0; j < 16; j++) s += s_m1[j] * s_h1[j][t];
        s_hbar[t] = s;
    } else if (t < 64) {
        const int l = t - 32;
        float s = 0.f;
#pragma unroll
        for (int j = 0; j < 16; j++) s += s_m3[j] * s_y2[j][l];
        s_ybar[l] = s;
    }
    __syncthreads();

    float gm0 = gc2_b[c0] + gc4_b[c0];
    float gm1 = gc2_b[c1] + gc4_b[c1];
#pragma unroll
    for (int l = 0; l < 32; l++) {
        float hb = s_hbar[l], yb = s_ybar[l];
        gm0 += hb * gc2_W[l * 512 + c0] + yb * gc4_W[l * 512 + c0];
        gm1 += hb * gc2_W[l * 512 + c1] + yb * gc4_W[l * 512 + c1];
    }
    feat[(size_t)gidx * 512 + c0] = fmaxf((om0 + 0.5f * gm0) * 0.5f, 0.f);
    feat[(size_t)gidx * 512 + c1] = fmaxf((om1 + 0.5f * gm1) * 0.5f, 0.f);
}

// ---------------------------------------------------------------------------
__global__ void reduce_T(const float* __restrict__ c, float* __restrict__ cbar)
{
    const int n = blockIdx.y;
    const int k = blockIdx.x * 256 + threadIdx.x;
    float s = 0.f;
#pragma unroll 8
    for (int tt = 0; tt < 64; tt++)
        s += c[(size_t)(n * 64 + tt) * 1024 + k];
    cbar[n * 1024 + k] = s * (1.f / 64.f);
}

__global__ __launch_bounds__(512) void clf_kernel(
    const float* __restrict__ cbar, const float* __restrict__ W,
    const float* __restrict__ b, float* __restrict__ out)
{
    __shared__ float sc[1024];
    const int n = blockIdx.x;
    for (int k = threadIdx.x; k < 1024; k += 512) sc[k] = cbar[n * 1024 + k];
    __syncthreads();
    const int j = threadIdx.x;
    if (j < 500) {
        float acc = b[j];
        for (int k = 0; k < 1024; k++) acc += sc[k] * W[k * 500 + j];
        out[n * 500 + j] = acc;
    }
}

// ---------------------------------------------------------------------------
extern "C" void kernel_launch(void* const* d_in, const int* in_sizes, int n_in,
                              void* d_out, int out_size)
{
    const float* object_raw = (const float*)d_in[0];
    const float* action_raw = (const float*)d_in[1];
    const float* W_obj = (const float*)d_in[2];
    const float* b_obj = (const float*)d_in[3];
    const float* W_act = (const float*)d_in[4];
    const float* b_act = (const float*)d_in[5];
    const float* gc1_W = (const float*)d_in[6];
    const float* gc1_b = (const float*)d_in[7];
    const float* gc2_W = (const float*)d_in[8];
    const float* gc2_b = (const float*)d_in[9];
    const float* gc3_W = (const float*)d_in[10];
    const float* gc3_b = (const float*)d_in[11];
    const float* gc4_W = (const float*)d_in[12];
    const float* gc4_b = (const float*)d_in[13];
    const float* fc1_W = (const float*)d_in[14];
    const float* fc1_b = (const float*)d_in[15];
    const float* clf_W = (const float*)d_in[16];
    const float* clf_b = (const float*)d_in[17];
    float* out = (float*)d_out;

    float *p_obj, *p_feat, *p_c, *p_cbar;
    cudaGetSymbolAddress((void**)&p_obj, g_obj);
    cudaGetSymbolAddress((void**)&p_feat, g_feat);
    cudaGetSymbolAddress((void**)&p_c, g_c);
    cudaGetSymbolAddress((void**)&p_cbar, g_cbar);

    const int SMEM = (3 * 128 * AST + 3 * 32 * BST) * 4;  // 107,520 B
    static int smem_set = 0;
    cudaFuncSetAttribute(tgemm, cudaFuncAttributeMaxDynamicSharedMemorySize, SMEM);
    (void)smem_set;

    // 1) obj = relu(object_raw @ W_obj + b)  [32768,512] as [2048,16,512]
    tgemm<<<dim3(4, 256), 256, SMEM>>>(object_raw, W_obj, b_obj, p_obj, 512, 512, 512, 0);

    // 2) act = relu(action_raw @ W_act + b) -> middle frame (d=8) of each graph
    tgemm<<<dim3(4, 16), 256, SMEM>>>(action_raw, W_act, b_act, p_obj, 512, 512, 16 * 512, 8 * 512);

    // 3) per-graph GCN + D-mean fusion -> feat [2048,512]
    graph_kernel<<<2048, 256>>>(p_obj, gc1_W, gc1_b, gc2_W, gc2_b,
                                gc3_W, gc3_b, gc4_W, gc4_b, p_feat);

    // 4) c = relu(feat @ fc1_W + b) [2048,1024]
    tgemm<<<dim3(8, 16), 256, SMEM>>>(p_feat, fc1_W, fc1_b, p_c, 512, 1024, 1024, 0);

    // 5) mean over T
    reduce_T<<<dim3(4, 32), 256>>>(p_c, p_cbar);

    // 6) out = cbar @ clf_W + clf_b  [32,500]
    clf_kernel<<<32, 512>>>(p_cbar, clf_W, clf_b, out);
}

// round 6
// speedup vs baseline: 2.0497x; 1.0013x over previous
#include <cuda_runtime.h>
#include <cstdint>
#include <cstddef>

// N=32, T=64, D=16, F=512; graphs = 2048. All big GEMM K = 512.

// -------- scratch (allocation-free) --------
__device__ float g_obj[2048 * 16 * 512];   // 64 MB
__device__ float g_feat[2048 * 512];       // 4 MB
__device__ float g_c[2048 * 1024];         // 8 MB
__device__ float g_cbar[32 * 1024];

#define DINL __device__ __forceinline__

DINL uint32_t s2u(const void* p) {
    uint32_t a;
    asm("{ .reg .u64 t; cvta.to.shared.u64 t, %1; cvt.u32.u64 %0, t; }" : "=r"(a) : "l"(p));
    return a;
}
DINL void cp16(uint32_t s, const void* g) {
    asm volatile("cp.async.cg.shared.global [%0], [%1], 16;" :: "r"(s), "l"(g));
}
DINL void cp_commit() { asm volatile("cp.async.commit_group;" ::: "memory"); }
DINL void cp_wait2()  { asm volatile("cp.async.wait_group 2;" ::: "memory"); }
DINL uint32_t f2tf(float f) {
    uint32_t u;
    asm("cvt.rna.tf32.f32 %0, %1;" : "=r"(u) : "f"(f));
    return u;
}
DINL void mma_tf32(float* c, const uint32_t* a, const uint32_t* b) {
    asm volatile(
        "mma.sync.aligned.m16n8k8.row.col.f32.tf32.tf32.f32 "
        "{%0,%1,%2,%3}, {%4,%5,%6,%7}, {%8,%9}, {%0,%1,%2,%3};"
        : "+f"(c[0]), "+f"(c[1]), "+f"(c[2]), "+f"(c[3])
        : "r"(a[0]), "r"(a[1]), "r"(a[2]), "r"(a[3]), "r"(b[0]), "r"(b[1]));
}

// ---------------------------------------------------------------------------
// Tensor-core tf32 GEMM: C[(bm+r)*ldc + coff + c] = relu(A@B + bias)
// A: [M,K] row-major; B: [K,Nb] row-major (natural weight layout, no transpose).
// BM=BN=128, BK=32, 3-stage cp.async pipeline, 256 thr = 8 warps (4x2),
// warp tile 32x64 = 2x8 m16n8k8 fragments. M%128==0, Nb%128? (grid covers), K%32==0.
// ---------------------------------------------------------------------------
#define AST 36   // A smem row stride (floats): banks 4g+tg unique, 144B = 9*16B
#define BST 136  // B smem row stride (floats): banks 8tg+g unique, 544B = 34*16B

__global__ __launch_bounds__(256) void tgemm(
    const float* __restrict__ A, const float* __restrict__ B,
    const float* __restrict__ bias, float* __restrict__ C,
    int K, int Nb, int ldc, int coff)
{
    extern __shared__ float smf[];
    float* sA = smf;                  // 3 stages * 128*36
    float* sB = smf + 3 * 128 * AST;  // 3 stages * 32*136

    const int t = threadIdx.x;
    const int lane = t & 31, wid = t >> 5;
    const int wm = wid & 3, wn = wid >> 2;       // warp grid 4x2
    const int g = lane >> 2, tg = lane & 3;      // fragment coords
    const long bm = (long)blockIdx.y * 128;
    const int bn = blockIdx.x * 128;
    const int nK = K >> 5;

    auto LOAD = [&](int j) {
        const int s = j % 3;
        float* a0 = sA + s * (128 * AST);
        float* b0 = sB + s * (32 * BST);
        const float* Ag = A + (size_t)bm * K + j * 32;
        const float* Bg = B + (size_t)(j * 32) * Nb + bn;
#pragma unroll
        for (int r = 0; r < 4; r++) {
            int i = t + 256 * r;
            int row = i >> 3, seg = i & 7;                     // A: 128 rows x 8 segs
            cp16(s2u(a0 + row * AST + seg * 4), Ag + (size_t)row * K + seg * 4);
            int kr = i >> 5, sg = i & 31;                      // B: 32 rows x 32 segs
            cp16(s2u(b0 + kr * BST + sg * 4), Bg + (size_t)kr * Nb + sg * 4);
        }
        cp_commit();
    };

    float acc[2][8][4];
#pragma unroll
    for (int m = 0; m < 2; m++)
#pragma unroll
        for (int n = 0; n < 8; n++)
#pragma unroll
            for (int q = 0; q < 4; q++) acc[m][n][q] = 0.f;

    LOAD(0); LOAD(1); LOAD(2);

    for (int i = 0; i < nK; i++) {
        cp_wait2();
        __syncthreads();
        const int s = i % 3;
        const float* As_ = sA + s * (128 * AST) + (wm * 32) * AST;
        const float* Bs_ = sB + s * (32 * BST) + wn * 64;
#pragma unroll
        for (int ks = 0; ks < 4; ks++) {
            uint32_t af[2][4];
#pragma unroll
            for (int m = 0; m < 2; m++) {
                const float* ap = As_ + (m * 16 + g) * AST + ks * 8 + tg;
                af[m][0] = f2tf(ap[0]);
                af[m][1] = f2tf(ap[8 * AST]);
                af[m][2] = f2tf(ap[4]);
                af[m][3] = f2tf(ap[8 * AST + 4]);
            }
            uint32_t bf[8][2];
#pragma unroll
            for (int n = 0; n < 8; n++) {
                const float* bp = Bs_ + (ks * 8 + tg) * BST + n * 8 + g;
                bf[n][0] = f2tf(bp[0]);
                bf[n][1] = f2tf(bp[4 * BST]);
            }
#pragma unroll
            for (int m = 0; m < 2; m++)
#pragma unroll
                for (int n = 0; n < 8; n++) mma_tf32(acc[m][n], af[m], bf[n]);
        }
        __syncthreads();
        if (i + 3 < nK) LOAD(i + 3);
    }

    // epilogue: bias + relu, float2 stores
#pragma unroll
    for (int m = 0; m < 2; m++) {
        const long row0 = bm + wm * 32 + m * 16 + g;
#pragma unroll
        for (int n = 0; n < 8; n++) {
            const int col = bn + wn * 64 + n * 8 + 2 * tg;
            const float b0 = bias[col], b1 = bias[col + 1];
            float2 v0, v1;
            v0.x = fmaxf(acc[m][n][0] + b0, 0.f);
            v0.y = fmaxf(acc[m][n][1] + b1, 0.f);
            v1.x = fmaxf(acc[m][n][2] + b0, 0.f);
            v1.y = fmaxf(acc[m][n][3] + b1, 0.f);
            *(float2*)(C + (size_t)row0 * ldc + coff + col) = v0;
            *(float2*)(C + (size_t)(row0 + 8) * ldc + coff + col) = v1;
        }
    }
}

// ---------------------------------------------------------------------------
// Per-graph GCN (known correct from round 0).
// ---------------------------------------------------------------------------
#define XS 516

__global__ __launch_bounds__(256) void graph_kernel(
    const float* __restrict__ obj,
    const float* __restrict__ gc1_W, const float* __restrict__ gc1_b,
    const float* __restrict__ gc2_W, const float* __restrict__ gc2_b,
    const float* __restrict__ gc3_W, const float* __restrict__ gc3_b,
    const float* __restrict__ gc4_W, const float* __restrict__ gc4_b,
    float* __restrict__ feat)
{
    __shared__ float sx[16 * XS];
    __shared__ float s_adj[16][17];
    __shared__ float s_a3[16][17];
    __shared__ float s_w1[16][33];
    __shared__ float s_w3[16][33];
    __shared__ float s_h1[16][33];
    __shared__ float s_y2[16][33];
    __shared__ float s_d[16], s_m1[16], s_m3[16];
    __shared__ float s_hbar[32], s_ybar[32];

    const int gidx = blockIdx.x;
    const int t = threadIdx.x;
    const float* x = obj + (size_t)gidx * 16 * 512;

    for (int idx = t * 4; idx < 16 * 512; idx += 256 * 4) {
        int i = idx >> 9, k = idx & 511;
        *(float4*)(sx + i * XS + k) = *(const float4*)(x + idx);
    }
    __syncthreads();

    const int c0 = t, c1 = t + 256;
    float om0 = 0.f, om1 = 0.f;
#pragma unroll
    for (int i = 0; i < 16; i++) { om0 += sx[i * XS + c0]; om1 += sx[i * XS + c1]; }
    om0 *= 0.0625f; om1 *= 0.0625f;

    {
        const int i = t >> 4, j = t & 15;
        float acc = 0.f;
        for (int k = 0; k < 512; k++) acc += sx[i * XS + k] * sx[j * XS + k];
        s_adj[i][j] = acc;
    }
    {
        const int j = t & 31, i0 = t >> 5;
        float a1a = 0, a1b = 0, a3a = 0, a3b = 0;
        for (int k = 0; k < 512; k++) {
            float w1 = gc1_W[k * 32 + j], w3 = gc3_W[k * 32 + j];
            float xa = sx[i0 * XS + k], xb = sx[(i0 + 8) * XS + k];
            a1a += xa * w1; a3a += xa * w3;
            a1b += xb * w1; a3b += xb * w3;
        }
        s_w1[i0][j] = a1a; s_w1[i0 + 8][j] = a1b;
        s_w3[i0][j] = a3a; s_w3[i0 + 8][j] = a3b;
    }
    __syncthreads();

    if (t < 16) {
        float mx = -1e30f;
#pragma unroll
        for (int j = 0; j < 16; j++) mx = fmaxf(mx, s_adj[t][j]);
        float sum = 0.f;
#pragma unroll
        for (int j = 0; j < 16; j++) { float e = expf(s_adj[t][j] - mx); s_adj[t][j] = e; sum += e; }
        s_d[t] = rsqrtf(sum);
    }
    __syncthreads();
    {
        const int i = t >> 4, j = t & 15;
        s_adj[i][j] = s_adj[i][j] * s_d[i] * s_d[j];
    }
    __syncthreads();

    if (t < 16) {
        float s = 0.f;
#pragma unroll
        for (int i = 0; i < 16; i++) s += s_adj[i][t];
        s_m1[t] = s * 0.0625f;
    }
    {
        const int j = t & 31, i0 = t >> 5;
#pragma unroll
        for (int rep = 0; rep < 2; rep++) {
            const int i = i0 + rep * 8;
            float a1 = gc1_b[j], a3 = gc3_b[j];
#pragma unroll
            for (int l = 0; l < 16; l++) {
                float ad = s_adj[i][l];
                a1 += ad * s_w1[l][j];
                a3 += ad * s_w3[l][j];
            }
            s_h1[i][j] = fmaxf(a1, 0.f);
            s_y2[i][j] = fmaxf(a3, 0.f);
        }
    }
    __syncthreads();

    {
        const int i = t >> 4, j = t & 15;
        float acc = 0.f;
#pragma unroll
        for (int l = 0; l < 32; l++) acc += s_y2[i][l] * s_y2[j][l];
        s_a3[i][j] = acc;
    }
    __syncthreads();
    if (t < 16) {
        float ss = 0.f;
#pragma unroll
        for (int j = 0; j < 16; j++) { float v = s_a3[t][j]; ss += v * v; }
        s_d[t] = sqrtf(ss);
    }
    __syncthreads();
    {
        const int i = t >> 4, j = t & 15;
        s_a3[i][j] = 1.f + s_a3[i][j] / (s_d[i] * s_d[j]);
    }
    __syncthreads();
    if (t < 16) {
        float sum = 0.f;
#pragma unroll
        for (int j = 0; j < 16; j++) sum += s_a3[t][j];
        s_d[t] = rsqrtf(sum);
    }
    __syncthreads();
    {
        const int i = t >> 4, j = t & 15;
        s_a3[i][j] = s_a3[i][j] * s_d[i] * s_d[j];
    }
    __syncthreads();
    if (t < 16) {
        float s = 0.f;
#pragma unroll
        for (int i = 0; i < 16; i++) s += s_a3[i][t];
        s_m3[t] = s * 0.0625f;
    }
    __syncthreads();

    if (t < 32) {
        float s = 0.f;
#pragma unroll
        for (int j = 0; j < 16; j++) s += s_m1[j] * s_h1[j][t];
        s_hbar[t] = s;
    } else if (t < 64) {
        const int l = t - 32;
        float s = 0.f;
#pragma unroll
        for (int j = 0; j < 16; j++) s += s_m3[j] * s_y2[j][l];
        s_ybar[l] = s;
    }
    __syncthreads();

    float gm0 = gc2_b[c0] + gc4_b[c0];
    float gm1 = gc2_b[c1] + gc4_b[c1];
#pragma unroll
    for (int l = 0; l < 32; l++) {
        float hb = s_hbar[l], yb = s_ybar[l];
        gm0 += hb * gc2_W[l * 512 + c0] + yb * gc4_W[l * 512 + c0];
        gm1 += hb * gc2_W[l * 512 + c1] + yb * gc4_W[l * 512 + c1];
    }
    feat[(size_t)gidx * 512 + c0] = fmaxf((om0 + 0.5f * gm0) * 0.5f, 0.f);
    feat[(size_t)gidx * 512 + c1] = fmaxf((om1 + 0.5f * gm1) * 0.5f, 0.f);
}

// ---------------------------------------------------------------------------
__global__ void reduce_T(const float* __restrict__ c, float* __restrict__ cbar)
{
    const int n = blockIdx.y;
    const int k = blockIdx.x * 256 + threadIdx.x;
    float s = 0.f;
#pragma unroll 8
    for (int tt = 0; tt < 64; tt++)
        s += c[(size_t)(n * 64 + tt) * 1024 + k];
    cbar[n * 1024 + k] = s * (1.f / 64.f);
}

__global__ __launch_bounds__(512) void clf_kernel(
    const float* __restrict__ cbar, const float* __restrict__ W,
    const float* __restrict__ b, float* __restrict__ out)
{
    __shared__ float sc[1024];
    const int n = blockIdx.x;
    for (int k = threadIdx.x; k < 1024; k += 512) sc[k] = cbar[n * 1024 + k];
    __syncthreads();
    const int j = threadIdx.x;
    if (j < 500) {
        float acc = b[j];
        for (int k = 0; k < 1024; k++) acc += sc[k] * W[k * 500 + j];
        out[n * 500 + j] = acc;
    }
}

// ---------------------------------------------------------------------------
extern "C" void kernel_launch(void* const* d_in, const int* in_sizes, int n_in,
                              void* d_out, int out_size)
{
    const float* object_raw = (const float*)d_in[0];
    const float* action_raw = (const float*)d_in[1];
    const float* W_obj = (const float*)d_in[2];
    const float* b_obj = (const float*)d_in[3];
    const float* W_act = (const float*)d_in[4];
    const float* b_act = (const float*)d_in[5];
    const float* gc1_W = (const float*)d_in[6];
    const float* gc1_b = (const float*)d_in[7];
    const float* gc2_W = (const float*)d_in[8];
    const float* gc2_b = (const float*)d_in[9];
    const float* gc3_W = (const float*)d_in[10];
    const float* gc3_b = (const float*)d_in[11];
    const float* gc4_W = (const float*)d_in[12];
    const float* gc4_b = (const float*)d_in[13];
    const float* fc1_W = (const float*)d_in[14];
    const float* fc1_b = (const float*)d_in[15];
    const float* clf_W = (const float*)d_in[16];
    const float* clf_b = (const float*)d_in[17];
    float* out = (float*)d_out;

    float *p_obj, *p_feat, *p_c, *p_cbar;
    cudaGetSymbolAddress((void**)&p_obj, g_obj);
    cudaGetSymbolAddress((void**)&p_feat, g_feat);
    cudaGetSymbolAddress((void**)&p_c, g_c);
    cudaGetSymbolAddress((void**)&p_cbar, g_cbar);

    const int SMEM = (3 * 128 * AST + 3 * 32 * BST) * 4;  // 107,520 B
    static int smem_set = 0;
    cudaFuncSetAttribute(tgemm, cudaFuncAttributeMaxDynamicSharedMemorySize, SMEM);
    (void)smem_set;

    // 1) obj = relu(object_raw @ W_obj + b)  [32768,512] as [2048,16,512]
    tgemm<<<dim3(4, 256), 256, SMEM>>>(object_raw, W_obj, b_obj, p_obj, 512, 512, 512, 0);

    // 2) act = relu(action_raw @ W_act + b) -> middle frame (d=8) of each graph
    tgemm<<<dim3(4, 16), 256, SMEM>>>(action_raw, W_act, b_act, p_obj, 512, 512, 16 * 512, 8 * 512);

    // 3) per-graph GCN + D-mean fusion -> feat [2048,512]
    graph_kernel<<<2048, 256>>>(p_obj, gc1_W, gc1_b, gc2_W, gc2_b,
                                gc3_W, gc3_b, gc4_W, gc4_b, p_feat);

    // 4) c = relu(feat @ fc1_W + b) [2048,1024]
    tgemm<<<dim3(8, 16), 256, SMEM>>>(p_feat, fc1_W, fc1_b, p_c, 512, 1024, 1024, 0);

    // 5) mean over T
    reduce_T<<<dim3(4, 32), 256>>>(p_c, p_cbar);

    // 6) out = cbar @ clf_W + clf_b  [32,500]
    clf_kernel<<<32, 512>>>(p_cbar, clf_W, clf_b, out);
}

// round 7
// speedup vs baseline: 2.9504x; 1.4394x over previous
#include <cuda_runtime.h>
#include <cstdint>
#include <cstddef>

// N=32, T=64, D=16, F=512; graphs = 2048.

// -------- scratch (allocation-free) --------
__device__ float g_obj[2048 * 16 * 512];   // 64 MB
__device__ float g_feat[2048 * 512];       // 4 MB
__device__ float g_c[2048 * 1024];         // 8 MB
__device__ float g_cbar[32 * 1024];
__device__ float g_xw[2048 * 16 * 64];     // 8 MB  (x @ [gc1_W|gc3_W])
__device__ float g_s[2048 * 256];          // 2 MB  (x @ x^T per graph)
__device__ float g_z[2048 * 64];           // hbar|ybar per graph
__device__ float g_om[2048 * 512];         // mean over D of obj
__device__ float g_gcW[512 * 64];          // packed [gc1_W | gc3_W]
__device__ float g_Wcat[64 * 512];         // packed [gc2_W ; gc4_W]
__device__ float g_bsum[512];              // gc2_b + gc4_b

#define DINL __device__ __forceinline__

DINL uint32_t s2u(const void* p) {
    uint32_t a;
    asm("{ .reg .u64 t; cvta.to.shared.u64 t, %1; cvt.u32.u64 %0, t; }" : "=r"(a) : "l"(p));
    return a;
}
DINL void cp16(uint32_t s, const void* g) {
    asm volatile("cp.async.cg.shared.global [%0], [%1], 16;" :: "r"(s), "l"(g));
}
DINL void cp_commit() { asm volatile("cp.async.commit_group;" ::: "memory"); }
DINL void cp_wait1()  { asm volatile("cp.async.wait_group 1;" ::: "memory"); }
DINL uint32_t f2tf(float f) {
    uint32_t u;
    asm("cvt.rna.tf32.f32 %0, %1;" : "=r"(u) : "f"(f));
    return u;
}
DINL void mma_tf32(float* c, const uint32_t* a, const uint32_t* b) {
    asm volatile(
        "mma.sync.aligned.m16n8k8.row.col.f32.tf32.tf32.f32 "
        "{%0,%1,%2,%3}, {%4,%5,%6,%7}, {%8,%9}, {%0,%1,%2,%3};"
        : "+f"(c[0]), "+f"(c[1]), "+f"(c[2]), "+f"(c[3])
        : "r"(a[0]), "r"(a[1]), "r"(a[2]), "r"(a[3]), "r"(b[0]), "r"(b[1]));
}

#define AST 36   // A smem row stride: fragment banks (4g+tg)%32 unique

// ---------------------------------------------------------------------------
// Tensor-core tf32 GEMM. A:[M,K] rm, B:[K,Nb] rm. BM=128, BN template (128/64),
// BK=32, 2-stage cp.async pipeline, 256 thr (8 warps, 4x2).
// EPI: 0 = relu(acc+bias);  1 = relu((om + 0.5*(acc+bias))*0.5);  2 = raw acc.
// ---------------------------------------------------------------------------
template <int BN, int EPI>
__global__ __launch_bounds__(256) void tgemm(
    const float* __restrict__ A, const float* __restrict__ B,
    const float* __restrict__ bias, const float* __restrict__ om,
    float* __restrict__ C, int K, int Nb, int ldc, int coff)
{
    constexpr int BSTc = (BN == 128) ? 136 : 72;   // banks (8tg+g)%32 unique
    constexpr int NF = BN / 16;                    // n-frags per warp
    extern __shared__ float smf[];
    float* sA = smf;                    // 2 stages * 128*AST
    float* sB = smf + 2 * 128 * AST;    // 2 stages * 32*BSTc

    const int t = threadIdx.x;
    const int lane = t & 31, wid = t >> 5;
    const int wm = wid & 3, wn = wid >> 2;
    const int g = lane >> 2, tg = lane & 3;
    const long bm = (long)blockIdx.y * 128;
    const int bn = blockIdx.x * BN;
    const int nK = K >> 5;

    auto LOAD = [&](int j) {
        const int s = j & 1;
        float* a0 = sA + s * (128 * AST);
        float* b0 = sB + s * (32 * BSTc);
        const float* Ag = A + (size_t)bm * K + j * 32;
        const float* Bg = B + (size_t)(j * 32) * Nb + bn;
#pragma unroll
        for (int r = 0; r < 4; r++) {
            int i = t + 256 * r;
            int row = i >> 3, seg = i & 7;
            cp16(s2u(a0 + row * AST + seg * 4), Ag + (size_t)row * K + seg * 4);
        }
        if (BN == 128) {
#pragma unroll
            for (int r = 0; r < 4; r++) {
                int i = t + 256 * r;
                int kr = i >> 5, sg = i & 31;
                cp16(s2u(b0 + kr * BSTc + sg * 4), Bg + (size_t)kr * Nb + sg * 4);
            }
        } else {
#pragma unroll
            for (int r = 0; r < 2; r++) {
                int i = t + 256 * r;
                int kr = i >> 4, sg = i & 15;
                cp16(s2u(b0 + kr * BSTc + sg * 4), Bg + (size_t)kr * Nb + sg * 4);
            }
        }
    };

    float acc[2][NF][4];
#pragma unroll
    for (int m = 0; m < 2; m++)
#pragma unroll
        for (int n = 0; n < NF; n++)
#pragma unroll
            for (int q = 0; q < 4; q++) acc[m][n][q] = 0.f;

    LOAD(0); cp_commit();
    LOAD(1); cp_commit();

    for (int i = 0; i < nK; i++) {
        cp_wait1();
        __syncthreads();
        const int s = i & 1;
        const float* As_ = sA + s * (128 * AST) + (wm * 32) * AST;
        const float* Bs_ = sB + s * (32 * BSTc) + wn * (BN / 2);
#pragma unroll
        for (int ks = 0; ks < 4; ks++) {
            uint32_t af[2][4];
#pragma unroll
            for (int m = 0; m < 2; m++) {
                const float* ap = As_ + (m * 16 + g) * AST + ks * 8 + tg;
                af[m][0] = f2tf(ap[0]);
                af[m][1] = f2tf(ap[8 * AST]);
                af[m][2] = f2tf(ap[4]);
                af[m][3] = f2tf(ap[8 * AST + 4]);
            }
            uint32_t bf[NF][2];
#pragma unroll
            for (int n = 0; n < NF; n++) {
                const float* bp = Bs_ + (ks * 8 + tg) * BSTc + n * 8 + g;
                bf[n][0] = f2tf(bp[0]);
                bf[n][1] = f2tf(bp[4 * BSTc]);
            }
#pragma unroll
            for (int m = 0; m < 2; m++)
#pragma unroll
                for (int n = 0; n < NF; n++) mma_tf32(acc[m][n], af[m], bf[n]);
        }
        __syncthreads();
        if (i + 2 < nK) LOAD(i + 2);
        cp_commit();
    }

#pragma unroll
    for (int m = 0; m < 2; m++) {
        const long row0 = bm + wm * 32 + m * 16 + g;
#pragma unroll
        for (int n = 0; n < NF; n++) {
            const int col = bn + wn * (BN / 2) + n * 8 + 2 * tg;
            float2 v0, v1;
            if (EPI == 2) {
                v0.x = acc[m][n][0]; v0.y = acc[m][n][1];
                v1.x = acc[m][n][2]; v1.y = acc[m][n][3];
            } else if (EPI == 0) {
                const float b0 = bias[col], b1 = bias[col + 1];
                v0.x = fmaxf(acc[m][n][0] + b0, 0.f);
                v0.y = fmaxf(acc[m][n][1] + b1, 0.f);
                v1.x = fmaxf(acc[m][n][2] + b0, 0.f);
                v1.y = fmaxf(acc[m][n][3] + b1, 0.f);
            } else {
                const float b0 = bias[col], b1 = bias[col + 1];
                float2 o0 = *(const float2*)(om + (size_t)row0 * ldc + col);
                float2 o1 = *(const float2*)(om + (size_t)(row0 + 8) * ldc + col);
                v0.x = fmaxf((o0.x + 0.5f * (acc[m][n][0] + b0)) * 0.5f, 0.f);
                v0.y = fmaxf((o0.y + 0.5f * (acc[m][n][1] + b1)) * 0.5f, 0.f);
                v1.x = fmaxf((o1.x + 0.5f * (acc[m][n][2] + b0)) * 0.5f, 0.f);
                v1.y = fmaxf((o1.y + 0.5f * (acc[m][n][3] + b1)) * 0.5f, 0.f);
            }
            *(float2*)(C + (size_t)row0 * ldc + coff + col) = v0;
            *(float2*)(C + (size_t)(row0 + 8) * ldc + coff + col) = v1;
        }
    }
}

// ---------------------------------------------------------------------------
// Batched x@x^T on tensor cores: 8 graphs per 128-row tile. B-fragments read
// TRANSPOSED from the same A tile (B = A^T). Each warp computes only its own
// 32x32 diagonal block; epilogue keeps the two 16x16 graph diagonals.
// ---------------------------------------------------------------------------
__global__ __launch_bounds__(128) void xxt_kernel(
    const float* __restrict__ A, float* __restrict__ S)
{
    __shared__ float sA[2 * 128 * AST];
    const int t = threadIdx.x, lane = t & 31, wid = t >> 5;
    const int g8 = lane >> 2, tg = lane & 3;
    const long bm = (long)blockIdx.x * 128;
    const int nK = 16;

    auto LOADA = [&](int j) {
        float* a0 = sA + (j & 1) * (128 * AST);
        const float* Ag = A + (size_t)bm * 512 + j * 32;
#pragma unroll
        for (int r = 0; r < 8; r++) {
            int i = t + 128 * r;
            int row = i >> 3, seg = i & 7;
            cp16(s2u(a0 + row * AST + seg * 4), Ag + (size_t)row * 512 + seg * 4);
        }
    };

    float acc[2][4][4];
#pragma unroll
    for (int m = 0; m < 2; m++)
#pragma unroll
        for (int n = 0; n < 4; n++)
#pragma unroll
            for (int q = 0; q < 4; q++) acc[m][n][q] = 0.f;

    LOADA(0); cp_commit();
    LOADA(1); cp_commit();

    for (int i = 0; i < nK; i++) {
        cp_wait1();
        __syncthreads();
        const float* As_ = sA + (i & 1) * (128 * AST) + (wid * 32) * AST;
#pragma unroll
        for (int ks = 0; ks < 4; ks++) {
            uint32_t af[2][4];
#pragma unroll
            for (int m = 0; m < 2; m++) {
                const float* ap = As_ + (m * 16 + g8) * AST + ks * 8 + tg;
                af[m][0] = f2tf(ap[0]);
                af[m][1] = f2tf(ap[8 * AST]);
                af[m][2] = f2tf(ap[4]);
                af[m][3] = f2tf(ap[8 * AST + 4]);
            }
            uint32_t bf[4][2];
#pragma unroll
            for (int n = 0; n < 4; n++) {  // B[k][c] = Atile[c][k] (transposed read)
                const float* bp = As_ + (n * 8 + g8) * AST + ks * 8 + tg;
                bf[n][0] = f2tf(bp[0]);
                bf[n][1] = f2tf(bp[4]);
            }
#pragma unroll
            for (int m = 0; m < 2; m++)
#pragma unroll
                for (int n = 0; n < 4; n++) mma_tf32(acc[m][n], af[m], bf[n]);
        }
        __syncthreads();
        if (i + 2 < nK) LOADA(i + 2);
        cp_commit();
    }

    // keep diagonal 16x16 blocks: warp wid, sub-block m -> graph wid*2+m
#pragma unroll
    for (int m = 0; m < 2; m++) {
        const long graph = blockIdx.x * 8 + wid * 2 + m;
        float* dst = S + graph * 256;
#pragma unroll
        for (int c = 0; c < 2; c++) {
            int n = 2 * m + c;
            int col = c * 8 + 2 * tg;
            dst[g8 * 16 + col]       = acc[m][n][0];
            dst[g8 * 16 + col + 1]   = acc[m][n][1];
            dst[(g8 + 8) * 16 + col]     = acc[m][n][2];
            dst[(g8 + 8) * 16 + col + 1] = acc[m][n][3];
        }
    }
}

// ---------------------------------------------------------------------------
// Small per-graph math on precomputed s=x@x^T and xw. 4 graphs per block.
// Emits z[g] = [hbar(32) | ybar(32)].
// ---------------------------------------------------------------------------
__global__ __launch_bounds__(256) void graph_small(
    const float* __restrict__ s_in, const float* __restrict__ xw,
    const float* __restrict__ gc1_b, const float* __restrict__ gc3_b,
    float* __restrict__ z)
{
    __shared__ float s_adj[4][16][17];
    __shared__ float s_a3[4][16][17];
    __shared__ float s_w1[4][16][33];
    __shared__ float s_w3[4][16][33];
    __shared__ float s_h1[4][16][33];
    __shared__ float s_y2[4][16][33];
    __shared__ float s_d[4][16], s_m1[4][16], s_m3[4][16];

    const int t = threadIdx.x, q = t >> 6, u = t & 63;
    const long g = (long)blockIdx.x * 4 + q;

#pragma unroll
    for (int r = 0; r < 4; r++) {
        int cell = u + 64 * r;
        s_adj[q][cell >> 4][cell & 15] = s_in[g * 256 + cell];
    }
#pragma unroll
    for (int r = 0; r < 16; r++) {
        float v = xw[g * 1024 + r * 64 + u];
        if (u < 32) s_w1[q][r][u] = v; else s_w3[q][r][u - 32] = v;
    }
    __syncthreads();

    if (u < 16) {
        float mx = -1e30f;
#pragma unroll
        for (int j = 0; j < 16; j++) mx = fmaxf(mx, s_adj[q][u][j]);
        float sum = 0.f;
#pragma unroll
        for (int j = 0; j < 16; j++) {
            float e = expf(s_adj[q][u][j] - mx);
            s_adj[q][u][j] = e; sum += e;
        }
        s_d[q][u] = rsqrtf(sum);
    }
    __syncthreads();
#pragma unroll
    for (int r = 0; r < 4; r++) {
        int cell = u + 64 * r, i = cell >> 4, j = cell & 15;
        s_adj[q][i][j] *= s_d[q][i] * s_d[q][j];
    }
    __syncthreads();
    if (u < 16) {
        float s = 0.f;
#pragma unroll
        for (int i = 0; i < 16; i++) s += s_adj[q][i][u];
        s_m1[q][u] = s * 0.0625f;
    }
    {
        const int j = u & 31, i0 = u >> 5;
#pragma unroll
        for (int rr = 0; rr < 8; rr++) {
            const int i = i0 + rr * 2;
            float a1 = gc1_b[j], a3 = gc3_b[j];
#pragma unroll
            for (int l = 0; l < 16; l++) {
                float ad = s_adj[q][i][l];
                a1 += ad * s_w1[q][l][j];
                a3 += ad * s_w3[q][l][j];
            }
            s_h1[q][i][j] = fmaxf(a1, 0.f);
            s_y2[q][i][j] = fmaxf(a3, 0.f);
        }
    }
    __syncthreads();

#pragma unroll
    for (int r = 0; r < 4; r++) {
        int cell = u + 64 * r, i = cell >> 4, j = cell & 15;
        float acc = 0.f;
#pragma unroll
        for (int l = 0; l < 32; l++) acc += s_y2[q][i][l] * s_y2[q][j][l];
        s_a3[q][i][j] = acc;
    }
    __syncthreads();
    if (u < 16) {
        float ss = 0.f;
#pragma unroll
        for (int j = 0; j < 16; j++) { float v = s_a3[q][u][j]; ss += v * v; }
        s_d[q][u] = sqrtf(ss);
    }
    __syncthreads();
#pragma unroll
    for (int r = 0; r < 4; r++) {
        int cell = u + 64 * r, i = cell >> 4, j = cell & 15;
        s_a3[q][i][j] = 1.f + s_a3[q][i][j] / (s_d[q][i] * s_d[q][j]);
    }
    __syncthreads();
    if (u < 16) {
        float sum = 0.f;
#pragma unroll
        for (int j = 0; j < 16; j++) sum += s_a3[q][u][j];
        s_d[q][u] = rsqrtf(sum);
    }
    __syncthreads();
#pragma unroll
    for (int r = 0; r < 4; r++) {
        int cell = u + 64 * r, i = cell >> 4, j = cell & 15;
        s_a3[q][i][j] *= s_d[q][i] * s_d[q][j];
    }
    __syncthreads();
    if (u < 16) {
        float s = 0.f;
#pragma unroll
        for (int i = 0; i < 16; i++) s += s_a3[q][i][u];
        s_m3[q][u] = s * 0.0625f;
    }
    __syncthreads();

    float zv;
    if (u < 32) {
        float s = 0.f;
#pragma unroll
        for (int j = 0; j < 16; j++) s += s_m1[q][j] * s_h1[q][j][u];
        zv = s;
    } else {
        const int l = u - 32;
        float s = 0.f;
#pragma unroll
        for (int j = 0; j < 16; j++) s += s_m3[q][j] * s_y2[q][j][l];
        zv = s;
    }
    z[g * 64 + u] = zv;
}

// ---------------------------------------------------------------------------
__global__ void om_kernel(const float* __restrict__ obj, float* __restrict__ om)
{
    const long g = blockIdx.x;
    const int c = threadIdx.x;
    const float* xg = obj + g * 8192;
    float s0 = 0.f, s1 = 0.f;
#pragma unroll
    for (int i = 0; i < 16; i++) { s0 += xg[i * 512 + c]; s1 += xg[i * 512 + c + 256]; }
    om[g * 512 + c] = s0 * 0.0625f;
    om[g * 512 + c + 256] = s1 * 0.0625f;
}

__global__ void pack_aux(
    const float* __restrict__ gc1W, const float* __restrict__ gc3W,
    const float* __restrict__ gc2W, const float* __restrict__ gc4W,
    const float* __restrict__ b2, const float* __restrict__ b4,
    float* __restrict__ gcW, float* __restrict__ Wcat, float* __restrict__ bsum)
{
    int i = blockIdx.x * 256 + threadIdx.x;   // 64 blocks -> 16384 threads
    { int k = i >> 5, j = i & 31;
      gcW[k * 64 + j] = gc1W[i];
      gcW[k * 64 + 32 + j] = gc3W[i]; }
    Wcat[i] = gc2W[i];
    Wcat[16384 + i] = gc4W[i];
    if (i < 512) bsum[i] = b2[i] + b4[i];
}

__global__ void reduce_T(const float* __restrict__ c, float* __restrict__ cbar)
{
    const int n = blockIdx.y;
    const int k = blockIdx.x * 256 + threadIdx.x;
    float s = 0.f;
#pragma unroll 8
    for (int tt = 0; tt < 64; tt++)
        s += c[(size_t)(n * 64 + tt) * 1024 + k];
    cbar[n * 1024 + k] = s * (1.f / 64.f);
}

__global__ __launch_bounds__(512) void clf_kernel(
    const float* __restrict__ cbar, const float* __restrict__ W,
    const float* __restrict__ b, float* __restrict__ out)
{
    __shared__ float sc[1024];
    const int n = blockIdx.x;
    for (int k = threadIdx.x; k < 1024; k += 512) sc[k] = cbar[n * 1024 + k];
    __syncthreads();
    const int j = threadIdx.x;
    if (j < 500) {
        float acc = b[j];
        for (int k = 0; k < 1024; k++) acc += sc[k] * W[k * 500 + j];
        out[n * 500 + j] = acc;
    }
}

// ---------------------------------------------------------------------------
extern "C" void kernel_launch(void* const* d_in, const int* in_sizes, int n_in,
                              void* d_out, int out_size)
{
    const float* object_raw = (const float*)d_in[0];
    const float* action_raw = (const float*)d_in[1];
    const float* W_obj = (const float*)d_in[2];
    const float* b_obj = (const float*)d_in[3];
    const float* W_act = (const float*)d_in[4];
    const float* b_act = (const float*)d_in[5];
    const float* gc1_W = (const float*)d_in[6];
    const float* gc1_b = (const float*)d_in[7];
    const float* gc2_W = (const float*)d_in[8];
    const float* gc2_b = (const float*)d_in[9];
    const float* gc3_W = (const float*)d_in[10];
    const float* gc3_b = (const float*)d_in[11];
    const float* gc4_W = (const float*)d_in[12];
    const float* gc4_b = (const float*)d_in[13];
    const float* fc1_W = (const float*)d_in[14];
    const float* fc1_b = (const float*)d_in[15];
    const float* clf_W = (const float*)d_in[16];
    const float* clf_b = (const float*)d_in[17];
    float* out = (float*)d_out;

    float *p_obj, *p_feat, *p_c, *p_cbar, *p_xw, *p_s, *p_z, *p_om, *p_gcW, *p_Wcat, *p_bsum;
    cudaGetSymbolAddress((void**)&p_obj, g_obj);
    cudaGetSymbolAddress((void**)&p_feat, g_feat);
    cudaGetSymbolAddress((void**)&p_c, g_c);
    cudaGetSymbolAddress((void**)&p_cbar, g_cbar);
    cudaGetSymbolAddress((void**)&p_xw, g_xw);
    cudaGetSymbolAddress((void**)&p_s, g_s);
    cudaGetSymbolAddress((void**)&p_z, g_z);
    cudaGetSymbolAddress((void**)&p_om, g_om);
    cudaGetSymbolAddress((void**)&p_gcW, g_gcW);
    cudaGetSymbolAddress((void**)&p_Wcat, g_Wcat);
    cudaGetSymbolAddress((void**)&p_bsum, g_bsum);

    const int SMEM128 = (2 * 128 * AST + 2 * 32 * 136) * 4;  // 71,680 B
    const int SMEM64  = (2 * 128 * AST + 2 * 32 * 72) * 4;   // 55,296 B
    cudaFuncSetAttribute(tgemm<128, 0>, cudaFuncAttributeMaxDynamicSharedMemorySize, SMEM128);
    cudaFuncSetAttribute(tgemm<128, 1>, cudaFuncAttributeMaxDynamicSharedMemorySize, SMEM128);
    cudaFuncSetAttribute(tgemm<64, 2>,  cudaFuncAttributeMaxDynamicSharedMemorySize, SMEM64);

    // 0) pack small weight aux buffers
    pack_aux<<<64, 256>>>(gc1_W, gc3_W, gc2_W, gc4_W, gc2_b, gc4_b,
                          p_gcW, p_Wcat, p_bsum);

    // 1) obj = relu(object_raw @ W_obj + b)  [32768,512] as [2048,16,512]
    tgemm<128, 0><<<dim3(4, 256), 256, SMEM128>>>(
        object_raw, W_obj, b_obj, nullptr, p_obj, 512, 512, 512, 0);

    // 2) act = relu(action_raw @ W_act + b) -> middle frame (d=8)
    tgemm<128, 0><<<dim3(4, 16), 256, SMEM128>>>(
        action_raw, W_act, b_act, nullptr, p_obj, 512, 512, 16 * 512, 8 * 512);

    // 3a) xw = obj @ [gc1_W|gc3_W]  [32768,64]
    tgemm<64, 2><<<dim3(1, 256), 256, SMEM64>>>(
        p_obj, p_gcW, nullptr, nullptr, p_xw, 512, 64, 64, 0);

    // 3b) s = x@x^T per graph (batched, diagonal blocks kept)
    xxt_kernel<<<256, 128>>>(p_obj, p_s);

    // 3c) omean over D
    om_kernel<<<2048, 256>>>(p_obj, p_om);

    // 3d) small per-graph math -> z = [hbar|ybar]
    graph_small<<<512, 256>>>(p_s, p_xw, gc1_b, gc3_b, p_z);

    // 3e) feat = relu((om + 0.5*(z@Wcat + bsum))*0.5)   [2048,512], K=64
    tgemm<128, 1><<<dim3(4, 16), 256, SMEM128>>>(
        p_z, p_Wcat, p_bsum, p_om, p_feat, 64, 512, 512, 0);

    // 4) c = relu(feat @ fc1_W + b) [2048,1024]
    tgemm<128, 0><<<dim3(8, 16), 256, SMEM128>>>(
        p_feat, fc1_W, fc1_b, nullptr, p_c, 512, 1024, 1024, 0);

    // 5) mean over T
    reduce_T<<<dim3(4, 32), 256>>>(p_c, p_cbar);

    // 6) out = cbar @ clf_W + clf_b  [32,500]
    clf_kernel<<<32, 512>>>(p_cbar, clf_W, clf_b, out);
}

// round 8
// speedup vs baseline: 2.9654x; 1.0051x over previous
#include <cuda_runtime.h>
#include <cstdint>
#include <cstddef>

// N=32, T=64, D=16, F=512; graphs = 2048.

// -------- scratch (allocation-free) --------
__device__ float g_obj[2048 * 16 * 512];   // 64 MB
__device__ float g_feat[2048 * 512];       // 4 MB
__device__ float g_c[2048 * 1024];         // 8 MB
__device__ float g_cbar[32 * 1024];
__device__ float g_xw[2048 * 16 * 64];     // 8 MB  (x @ [gc1_W|gc3_W])
__device__ float g_s[2048 * 256];          // 2 MB  (x @ x^T per graph)
__device__ float g_z[2048 * 64];           // hbar|ybar per graph
__device__ float g_om[2048 * 512];         // mean over D of obj
__device__ float g_gcW[512 * 64];          // packed [gc1_W | gc3_W]
__device__ float g_Wcat[64 * 512];         // packed [gc2_W ; gc4_W]
__device__ float g_bsum[512];              // gc2_b + gc4_b

#define DINL __device__ __forceinline__

DINL uint32_t s2u(const void* p) {
    uint32_t a;
    asm("{ .reg .u64 t; cvta.to.shared.u64 t, %1; cvt.u32.u64 %0, t; }" : "=r"(a) : "l"(p));
    return a;
}
DINL void cp16(uint32_t s, const void* g) {
    asm volatile("cp.async.cg.shared.global [%0], [%1], 16;" :: "r"(s), "l"(g));
}
DINL void cp_commit() { asm volatile("cp.async.commit_group;" ::: "memory"); }
DINL void cp_wait1()  { asm volatile("cp.async.wait_group 1;" ::: "memory"); }
DINL uint32_t f2tf(float f) {
    uint32_t u;
    asm("cvt.rna.tf32.f32 %0, %1;" : "=r"(u) : "f"(f));
    return u;
}
DINL void mma_tf32(float* c, const uint32_t* a, const uint32_t* b) {
    asm volatile(
        "mma.sync.aligned.m16n8k8.row.col.f32.tf32.tf32.f32 "
        "{%0,%1,%2,%3}, {%4,%5,%6,%7}, {%8,%9}, {%0,%1,%2,%3};"
        : "+f"(c[0]), "+f"(c[1]), "+f"(c[2]), "+f"(c[3])
        : "r"(a[0]), "r"(a[1]), "r"(a[2]), "r"(a[3]), "r"(b[0]), "r"(b[1]));
}

#define AST 36   // A smem row stride: fragment banks (4g+tg)%32 unique

// ---------------------------------------------------------------------------
// Tensor-core tf32 GEMM. A:[M,K] rm, B:[K,Nb] rm. BM=128, BN template (128/64),
// BK=32, 2-stage cp.async pipeline, 256 thr (8 warps, 4x2).
// EPI: 0 = relu(acc+bias);  1 = relu((om + 0.5*(acc+bias))*0.5);  2 = raw acc.
// ---------------------------------------------------------------------------
template <int BN, int EPI>
__global__ __launch_bounds__(256) void tgemm(
    const float* __restrict__ A, const float* __restrict__ B,
    const float* __restrict__ bias, const float* __restrict__ om,
    float* __restrict__ C, int K, int Nb, int ldc, int coff)
{
    constexpr int BSTc = (BN == 128) ? 136 : 72;   // banks (8tg+g)%32 unique
    constexpr int NF = BN / 16;                    // n-frags per warp
    extern __shared__ float smf[];
    float* sA = smf;                    // 2 stages * 128*AST
    float* sB = smf + 2 * 128 * AST;    // 2 stages * 32*BSTc

    const int t = threadIdx.x;
    const int lane = t & 31, wid = t >> 5;
    const int wm = wid & 3, wn = wid >> 2;
    const int g = lane >> 2, tg = lane & 3;
    const long bm = (long)blockIdx.y * 128;
    const int bn = blockIdx.x * BN;
    const int nK = K >> 5;

    auto LOAD = [&](int j) {
        const int s = j & 1;
        float* a0 = sA + s * (128 * AST);
        float* b0 = sB + s * (32 * BSTc);
        const float* Ag = A + (size_t)bm * K + j * 32;
        const float* Bg = B + (size_t)(j * 32) * Nb + bn;
#pragma unroll
        for (int r = 0; r < 4; r++) {
            int i = t + 256 * r;
            int row = i >> 3, seg = i & 7;
            cp16(s2u(a0 + row * AST + seg * 4), Ag + (size_t)row * K + seg * 4);
        }
        if (BN == 128) {
#pragma unroll
            for (int r = 0; r < 4; r++) {
                int i = t + 256 * r;
                int kr = i >> 5, sg = i & 31;
                cp16(s2u(b0 + kr * BSTc + sg * 4), Bg + (size_t)kr * Nb + sg * 4);
            }
        } else {
#pragma unroll
            for (int r = 0; r < 2; r++) {
                int i = t + 256 * r;
                int kr = i >> 4, sg = i & 15;
                cp16(s2u(b0 + kr * BSTc + sg * 4), Bg + (size_t)kr * Nb + sg * 4);
            }
        }
    };

    float acc[2][NF][4];
#pragma unroll
    for (int m = 0; m < 2; m++)
#pragma unroll
        for (int n = 0; n < NF; n++)
#pragma unroll
            for (int q = 0; q < 4; q++) acc[m][n][q] = 0.f;

    LOAD(0); cp_commit();
    LOAD(1); cp_commit();

    for (int i = 0; i < nK; i++) {
        cp_wait1();
        __syncthreads();
        const int s = i & 1;
        const float* As_ = sA + s * (128 * AST) + (wm * 32) * AST;
        const float* Bs_ = sB + s * (32 * BSTc) + wn * (BN / 2);
#pragma unroll
        for (int ks = 0; ks < 4; ks++) {
            uint32_t af[2][4];
#pragma unroll
            for (int m = 0; m < 2; m++) {
                const float* ap = As_ + (m * 16 + g) * AST + ks * 8 + tg;
                af[m][0] = f2tf(ap[0]);
                af[m][1] = f2tf(ap[8 * AST]);
                af[m][2] = f2tf(ap[4]);
                af[m][3] = f2tf(ap[8 * AST + 4]);
            }
            uint32_t bf[NF][2];
#pragma unroll
            for (int n = 0; n < NF; n++) {
                const float* bp = Bs_ + (ks * 8 + tg) * BSTc + n * 8 + g;
                bf[n][0] = f2tf(bp[0]);
                bf[n][1] = f2tf(bp[4 * BSTc]);
            }
#pragma unroll
            for (int m = 0; m < 2; m++)
#pragma unroll
                for (int n = 0; n < NF; n++) mma_tf32(acc[m][n], af[m], bf[n]);
        }
        __syncthreads();
        if (i + 2 < nK) LOAD(i + 2);
        cp_commit();
    }

#pragma unroll
    for (int m = 0; m < 2; m++) {
        const long row0 = bm + wm * 32 + m * 16 + g;
#pragma unroll
        for (int n = 0; n < NF; n++) {
            const int col = bn + wn * (BN / 2) + n * 8 + 2 * tg;
            float2 v0, v1;
            if (EPI == 2) {
                v0.x = acc[m][n][0]; v0.y = acc[m][n][1];
                v1.x = acc[m][n][2]; v1.y = acc[m][n][3];
            } else if (EPI == 0) {
                const float b0 = bias[col], b1 = bias[col + 1];
                v0.x = fmaxf(acc[m][n][0] + b0, 0.f);
                v0.y = fmaxf(acc[m][n][1] + b1, 0.f);
                v1.x = fmaxf(acc[m][n][2] + b0, 0.f);
                v1.y = fmaxf(acc[m][n][3] + b1, 0.f);
            } else {
                const float b0 = bias[col], b1 = bias[col + 1];
                float2 o0 = *(const float2*)(om + (size_t)row0 * ldc + col);
                float2 o1 = *(const float2*)(om + (size_t)(row0 + 8) * ldc + col);
                v0.x = fmaxf((o0.x + 0.5f * (acc[m][n][0] + b0)) * 0.5f, 0.f);
                v0.y = fmaxf((o0.y + 0.5f * (acc[m][n][1] + b1)) * 0.5f, 0.f);
                v1.x = fmaxf((o1.x + 0.5f * (acc[m][n][2] + b0)) * 0.5f, 0.f);
                v1.y = fmaxf((o1.y + 0.5f * (acc[m][n][3] + b1)) * 0.5f, 0.f);
            }
            *(float2*)(C + (size_t)row0 * ldc + coff + col) = v0;
            *(float2*)(C + (size_t)(row0 + 8) * ldc + coff + col) = v1;
        }
    }
}

// ---------------------------------------------------------------------------
// Batched x@x^T on tensor cores: 8 graphs per 128-row tile. B-fragments read
// TRANSPOSED from the same A tile (B = A^T). Each warp computes only its own
// 32x32 diagonal block; epilogue keeps the two 16x16 graph diagonals.
// ---------------------------------------------------------------------------
__global__ __launch_bounds__(128) void xxt_kernel(
    const float* __restrict__ A, float* __restrict__ S)
{
    __shared__ float sA[2 * 128 * AST];
    const int t = threadIdx.x, lane = t & 31, wid = t >> 5;
    const int g8 = lane >> 2, tg = lane & 3;
    const long bm = (long)blockIdx.x * 128;
    const int nK = 16;

    auto LOADA = [&](int j) {
        float* a0 = sA + (j & 1) * (128 * AST);
        const float* Ag = A + (size_t)bm * 512 + j * 32;
#pragma unroll
        for (int r = 0; r < 8; r++) {
            int i = t + 128 * r;
            int row = i >> 3, seg = i & 7;
            cp16(s2u(a0 + row * AST + seg * 4), Ag + (size_t)row * 512 + seg * 4);
        }
    };

    float acc[2][4][4];
#pragma unroll
    for (int m = 0; m < 2; m++)
#pragma unroll
        for (int n = 0; n < 4; n++)
#pragma unroll
            for (int q = 0; q < 4; q++) acc[m][n][q] = 0.f;

    LOADA(0); cp_commit();
    LOADA(1); cp_commit();

    for (int i = 0; i < nK; i++) {
        cp_wait1();
        __syncthreads();
        const float* As_ = sA + (i & 1) * (128 * AST) + (wid * 32) * AST;
#pragma unroll
        for (int ks = 0; ks < 4; ks++) {
            uint32_t af[2][4];
#pragma unroll
            for (int m = 0; m < 2; m++) {
                const float* ap = As_ + (m * 16 + g8) * AST + ks * 8 + tg;
                af[m][0] = f2tf(ap[0]);
                af[m][1] = f2tf(ap[8 * AST]);
                af[m][2] = f2tf(ap[4]);
                af[m][3] = f2tf(ap[8 * AST + 4]);
            }
            uint32_t bf[4][2];
#pragma unroll
            for (int n = 0; n < 4; n++) {  // B[k][c] = Atile[c][k] (transposed read)
                const float* bp = As_ + (n * 8 + g8) * AST + ks * 8 + tg;
                bf[n][0] = f2tf(bp[0]);
                bf[n][1] = f2tf(bp[4]);
            }
#pragma unroll
            for (int m = 0; m < 2; m++)
#pragma unroll
                for (int n = 0; n < 4; n++) mma_tf32(acc[m][n], af[m], bf[n]);
        }
        __syncthreads();
        if (i + 2 < nK) LOADA(i + 2);
        cp_commit();
    }

    // keep diagonal 16x16 blocks: warp wid, sub-block m -> graph wid*2+m
#pragma unroll
    for (int m = 0; m < 2; m++) {
        const long graph = blockIdx.x * 8 + wid * 2 + m;
        float* dst = S + graph * 256;
#pragma unroll
        for (int c = 0; c < 2; c++) {
            int n = 2 * m + c;
            int col = c * 8 + 2 * tg;
            dst[g8 * 16 + col]       = acc[m][n][0];
            dst[g8 * 16 + col + 1]   = acc[m][n][1];
            dst[(g8 + 8) * 16 + col]     = acc[m][n][2];
            dst[(g8 + 8) * 16 + col + 1] = acc[m][n][3];
        }
    }
}

// ---------------------------------------------------------------------------
// Small per-graph math on precomputed s=x@x^T and xw. 4 graphs per block.
// Emits z[g] = [hbar(32) | ybar(32)].
// ---------------------------------------------------------------------------
__global__ __launch_bounds__(256) void graph_small(
    const float* __restrict__ s_in, const float* __restrict__ xw,
    const float* __restrict__ gc1_b, const float* __restrict__ gc3_b,
    float* __restrict__ z)
{
    __shared__ float s_adj[4][16][17];
    __shared__ float s_a3[4][16][17];
    __shared__ float s_w1[4][16][33];
    __shared__ float s_w3[4][16][33];
    __shared__ float s_h1[4][16][33];
    __shared__ float s_y2[4][16][33];
    __shared__ float s_d[4][16], s_m1[4][16], s_m3[4][16];

    const int t = threadIdx.x, q = t >> 6, u = t & 63;
    const long g = (long)blockIdx.x * 4 + q;

#pragma unroll
    for (int r = 0; r < 4; r++) {
        int cell = u + 64 * r;
        s_adj[q][cell >> 4][cell & 15] = s_in[g * 256 + cell];
    }
#pragma unroll
    for (int r = 0; r < 16; r++) {
        float v = xw[g * 1024 + r * 64 + u];
        if (u < 32) s_w1[q][r][u] = v; else s_w3[q][r][u - 32] = v;
    }
    __syncthreads();

    if (u < 16) {
        float mx = -1e30f;
#pragma unroll
        for (int j = 0; j < 16; j++) mx = fmaxf(mx, s_adj[q][u][j]);
        float sum = 0.f;
#pragma unroll
        for (int j = 0; j < 16; j++) {
            float e = expf(s_adj[q][u][j] - mx);
            s_adj[q][u][j] = e; sum += e;
        }
        s_d[q][u] = rsqrtf(sum);
    }
    __syncthreads();
#pragma unroll
    for (int r = 0; r < 4; r++) {
        int cell = u + 64 * r, i = cell >> 4, j = cell & 15;
        s_adj[q][i][j] *= s_d[q][i] * s_d[q][j];
    }
    __syncthreads();
    if (u < 16) {
        float s = 0.f;
#pragma unroll
        for (int i = 0; i < 16; i++) s += s_adj[q][i][u];
        s_m1[q][u] = s * 0.0625f;
    }
    {
        const int j = u & 31, i0 = u >> 5;
#pragma unroll
        for (int rr = 0; rr < 8; rr++) {
            const int i = i0 + rr * 2;
            float a1 = gc1_b[j], a3 = gc3_b[j];
#pragma unroll
            for (int l = 0; l < 16; l++) {
                float ad = s_adj[q][i][l];
                a1 += ad * s_w1[q][l][j];
                a3 += ad * s_w3[q][l][j];
            }
            s_h1[q][i][j] = fmaxf(a1, 0.f);
            s_y2[q][i][j] = fmaxf(a3, 0.f);
        }
    }
    __syncthreads();

#pragma unroll
    for (int r = 0; r < 4; r++) {
        int cell = u + 64 * r, i = cell >> 4, j = cell & 15;
        float acc = 0.f;
#pragma unroll
        for (int l = 0; l < 32; l++) acc += s_y2[q][i][l] * s_y2[q][j][l];
        s_a3[q][i][j] = acc;
    }
    __syncthreads();
    if (u < 16) {
        float ss = 0.f;
#pragma unroll
        for (int j = 0; j < 16; j++) { float v = s_a3[q][u][j]; ss += v * v; }
        s_d[q][u] = sqrtf(ss);
    }
    __syncthreads();
#pragma unroll
    for (int r = 0; r < 4; r++) {
        int cell = u + 64 * r, i = cell >> 4, j = cell & 15;
        s_a3[q][i][j] = 1.f + s_a3[q][i][j] / (s_d[q][i] * s_d[q][j]);
    }
    __syncthreads();
    if (u < 16) {
        float sum = 0.f;
#pragma unroll
        for (int j = 0; j < 16; j++) sum += s_a3[q][u][j];
        s_d[q][u] = rsqrtf(sum);
    }
    __syncthreads();
#pragma unroll
    for (int r = 0; r < 4; r++) {
        int cell = u + 64 * r, i = cell >> 4, j = cell & 15;
        s_a3[q][i][j] *= s_d[q][i] * s_d[q][j];
    }
    __syncthreads();
    if (u < 16) {
        float s = 0.f;
#pragma unroll
        for (int i = 0; i < 16; i++) s += s_a3[q][i][u];
        s_m3[q][u] = s * 0.0625f;
    }
    __syncthreads();

    float zv;
    if (u < 32) {
        float s = 0.f;
#pragma unroll
        for (int j = 0; j < 16; j++) s += s_m1[q][j] * s_h1[q][j][u];
        zv = s;
    } else {
        const int l = u - 32;
        float s = 0.f;
#pragma unroll
        for (int j = 0; j < 16; j++) s += s_m3[q][j] * s_y2[q][j][l];
        zv = s;
    }
    z[g * 64 + u] = zv;
}

// ---------------------------------------------------------------------------
__global__ void om_kernel(const float* __restrict__ obj, float* __restrict__ om)
{
    const long g = blockIdx.x;
    const int c = threadIdx.x;
    const float* xg = obj + g * 8192;
    float s0 = 0.f, s1 = 0.f;
#pragma unroll
    for (int i = 0; i < 16; i++) { s0 += xg[i * 512 + c]; s1 += xg[i * 512 + c + 256]; }
    om[g * 512 + c] = s0 * 0.0625f;
    om[g * 512 + c + 256] = s1 * 0.0625f;
}

__global__ void pack_aux(
    const float* __restrict__ gc1W, const float* __restrict__ gc3W,
    const float* __restrict__ gc2W, const float* __restrict__ gc4W,
    const float* __restrict__ b2, const float* __restrict__ b4,
    float* __restrict__ gcW, float* __restrict__ Wcat, float* __restrict__ bsum)
{
    int i = blockIdx.x * 256 + threadIdx.x;   // 64 blocks -> 16384 threads
    { int k = i >> 5, j = i & 31;
      gcW[k * 64 + j] = gc1W[i];
      gcW[k * 64 + 32 + j] = gc3W[i]; }
    Wcat[i] = gc2W[i];
    Wcat[16384 + i] = gc4W[i];
    if (i < 512) bsum[i] = b2[i] + b4[i];
}

__global__ void reduce_T(const float* __restrict__ c, float* __restrict__ cbar)
{
    const int n = blockIdx.y;
    const int k = blockIdx.x * 256 + threadIdx.x;
    float s = 0.f;
#pragma unroll 8
    for (int tt = 0; tt < 64; tt++)
        s += c[(size_t)(n * 64 + tt) * 1024 + k];
    cbar[n * 1024 + k] = s * (1.f / 64.f);
}

__global__ __launch_bounds__(512) void clf_kernel(
    const float* __restrict__ cbar, const float* __restrict__ W,
    const float* __restrict__ b, float* __restrict__ out)
{
    __shared__ float sc[1024];
    const int n = blockIdx.x;
    for (int k = threadIdx.x; k < 1024; k += 512) sc[k] = cbar[n * 1024 + k];
    __syncthreads();
    const int j = threadIdx.x;
    if (j < 500) {
        float acc = b[j];
        for (int k = 0; k < 1024; k++) acc += sc[k] * W[k * 500 + j];
        out[n * 500 + j] = acc;
    }
}

// ---------------------------------------------------------------------------
extern "C" void kernel_launch(void* const* d_in, const int* in_sizes, int n_in,
                              void* d_out, int out_size)
{
    const float* object_raw = (const float*)d_in[0];
    const float* action_raw = (const float*)d_in[1];
    const float* W_obj = (const float*)d_in[2];
    const float* b_obj = (const float*)d_in[3];
    const float* W_act = (const float*)d_in[4];
    const float* b_act = (const float*)d_in[5];
    const float* gc1_W = (const float*)d_in[6];
    const float* gc1_b = (const float*)d_in[7];
    const float* gc2_W = (const float*)d_in[8];
    const float* gc2_b = (const float*)d_in[9];
    const float* gc3_W = (const float*)d_in[10];
    const float* gc3_b = (const float*)d_in[11];
    const float* gc4_W = (const float*)d_in[12];
    const float* gc4_b = (const float*)d_in[13];
    const float* fc1_W = (const float*)d_in[14];
    const float* fc1_b = (const float*)d_in[15];
    const float* clf_W = (const float*)d_in[16];
    const float* clf_b = (const float*)d_in[17];
    float* out = (float*)d_out;

    float *p_obj, *p_feat, *p_c, *p_cbar, *p_xw, *p_s, *p_z, *p_om, *p_gcW, *p_Wcat, *p_bsum;
    cudaGetSymbolAddress((void**)&p_obj, g_obj);
    cudaGetSymbolAddress((void**)&p_feat, g_feat);
    cudaGetSymbolAddress((void**)&p_c, g_c);
    cudaGetSymbolAddress((void**)&p_cbar, g_cbar);
    cudaGetSymbolAddress((void**)&p_xw, g_xw);
    cudaGetSymbolAddress((void**)&p_s, g_s);
    cudaGetSymbolAddress((void**)&p_z, g_z);
    cudaGetSymbolAddress((void**)&p_om, g_om);
    cudaGetSymbolAddress((void**)&p_gcW, g_gcW);
    cudaGetSymbolAddress((void**)&p_Wcat, g_Wcat);
    cudaGetSymbolAddress((void**)&p_bsum, g_bsum);

    const int SMEM128 = (2 * 128 * AST + 2 * 32 * 136) * 4;  // 71,680 B
    const int SMEM64  = (2 * 128 * AST + 2 * 32 * 72) * 4;   // 55,296 B
    cudaFuncSetAttribute(tgemm<128, 0>, cudaFuncAttributeMaxDynamicSharedMemorySize, SMEM128);
    cudaFuncSetAttribute(tgemm<128, 1>, cudaFuncAttributeMaxDynamicSharedMemorySize, SMEM128);
    cudaFuncSetAttribute(tgemm<64, 2>,  cudaFuncAttributeMaxDynamicSharedMemorySize, SMEM64);

    // 0) pack small weight aux buffers
    pack_aux<<<64, 256>>>(gc1_W, gc3_W, gc2_W, gc4_W, gc2_b, gc4_b,
                          p_gcW, p_Wcat, p_bsum);

    // 1) obj = relu(object_raw @ W_obj + b)  [32768,512] as [2048,16,512]
    tgemm<128, 0><<<dim3(4, 256), 256, SMEM128>>>(
        object_raw, W_obj, b_obj, nullptr, p_obj, 512, 512, 512, 0);

    // 2) act = relu(action_raw @ W_act + b) -> middle frame (d=8)
    tgemm<128, 0><<<dim3(4, 16), 256, SMEM128>>>(
        action_raw, W_act, b_act, nullptr, p_obj, 512, 512, 16 * 512, 8 * 512);

    // 3a) xw = obj @ [gc1_W|gc3_W]  [32768,64]
    tgemm<64, 2><<<dim3(1, 256), 256, SMEM64>>>(
        p_obj, p_gcW, nullptr, nullptr, p_xw, 512, 64, 64, 0);

    // 3b) s = x@x^T per graph (batched, diagonal blocks kept)
    xxt_kernel<<<256, 128>>>(p_obj, p_s);

    // 3c) omean over D
    om_kernel<<<2048, 256>>>(p_obj, p_om);

    // 3d) small per-graph math -> z = [hbar|ybar]
    graph_small<<<512, 256>>>(p_s, p_xw, gc1_b, gc3_b, p_z);

    // 3e) feat = relu((om + 0.5*(z@Wcat + bsum))*0.5)   [2048,512], K=64
    tgemm<128, 1><<<dim3(4, 16), 256, SMEM128>>>(
        p_z, p_Wcat, p_bsum, p_om, p_feat, 64, 512, 512, 0);

    // 4) c = relu(feat @ fc1_W + b) [2048,1024]
    tgemm<128, 0><<<dim3(8, 16), 256, SMEM128>>>(
        p_feat, fc1_W, fc1_b, nullptr, p_c, 512, 1024, 1024, 0);

    // 5) mean over T
    reduce_T<<<dim3(4, 32), 256>>>(p_c, p_cbar);

    // 6) out = cbar @ clf_W + clf_b  [32,500]
    clf_kernel<<<32, 512>>>(p_cbar, clf_W, clf_b, out);
}